// round 4
// baseline (speedup 1.0000x reference)
#include <cuda_runtime.h>

#define W   30
#define TT  4096
#define FF  128
#define NS  (TT - W + 1)      // 4067 window starts
#define SEG 120               // 4 * 30 — grid (64,34)=2176 CTAs: single wave, 14.7 CTA/SM
#define NGROUPS (SEG / W)     // 4
#define EPSF 1e-4f

__global__ __launch_bounds__(FF)
void ts_zscore_kernel(const float* __restrict__ x, float* __restrict__ out)
{
    const int f = threadIdx.x;          // feature column
    const int b = blockIdx.x;           // batch
    int k0 = blockIdx.y * SEG;          // first window start handled by this block
    if (k0 > NS - SEG) k0 = NS - SEG;   // clamp: last block overlaps prior (same values)

    const float* __restrict__ xp = x   + ((size_t)b * TT + k0) * FF + f;
    float*       __restrict__ op = out + ((size_t)b * NS + k0) * FF + f;

    float s = 0.0f, s2 = 0.0f;

    // Prime with the first 29 values x[k0 .. k0+28] (also warms L1 for the
    // ov re-loads below).
#pragma unroll
    for (int i = 0; i < W - 1; ++i) {
        const float val = __ldg(xp + (size_t)i * FF);
        s += val;
        s2 = fmaf(val, val, s2);
    }

#pragma unroll 1
    for (int g = 0; g < NGROUPS; ++g) {
#pragma unroll
        for (int u = 0; u < W; ++u) {
            // New element entering the window for output u: x[.. + u + 29]
            const float nv = __ldg(xp + (size_t)(u + W - 1) * FF);

            const float ss  = s + nv;           // window sum
            const float ss2 = fmaf(nv, nv, s2);

            const float mean   = ss  * (1.0f / W);
            const float meansq = ss2 * (1.0f / W);
            float var = fmaf(-mean, mean, meansq);
            var = fmaxf(var, 0.0f);

            float stdv;
            asm("sqrt.approx.f32 %0, %1;" : "=f"(stdv) : "f"(var));
            const float r = __fdividef(nv - mean, stdv + EPSF);

            __stcs(op + (size_t)u * FF, r);     // streaming store: write-once data

            // Element leaving the window: re-load x[.. + u] — it was this
            // thread's nv 29 iterations ago, so it's an L1/L2 hit.
            const float ov = __ldg(xp + (size_t)u * FF);
            s  = ss  - ov;
            s2 = fmaf(-ov, ov, ss2);
        }
        xp += (size_t)W * FF;
        op += (size_t)W * FF;
    }
}

extern "C" void kernel_launch(void* const* d_in, const int* in_sizes, int n_in,
                              void* d_out, int out_size)
{
    (void)n_in; (void)out_size;
    const float* x = (const float*)d_in[0];
    float* out = (float*)d_out;

    const int B = in_sizes[0] / (TT * FF);   // 64 for this problem
    dim3 grid(B, (NS + SEG - 1) / SEG);      // (64, 34)
    ts_zscore_kernel<<<grid, FF>>>(x, out);
}